// round 7
// baseline (speedup 1.0000x reference)
#include <cuda_runtime.h>
#include <math.h>

#define NB 128
#define NC 1000
#define ND 300
#define NL 40
#define NH 100

// ---------------- scratch (device globals; no allocation allowed) ----------
__device__ float g_Wcat[1800 * 300];      // stacked conv weights [6D, D]
__device__ float g_catSV[1000 * 600];     // concat(slot_emb, value_emb)
__device__ float g_G[5120 * 1800];        // conv pre-activations, [B*L, 6D]
__device__ float g_fu[NB * ND];           // final_utt [B, D]
__device__ float g_fuT[ND * NB];          // final_utt^T [D, B]
__device__ float g_cand[NC * ND];         // sigmoid(candidates transform)
__device__ float g_P[NC * NB];            // slot_emb @ sys_slots^T
__device__ float g_Q[NC * NB];            // (slot@conf_s^T)*(value@conf_v^T)
__device__ float g_mr[NC * ND];
__device__ float g_mc[NC * ND];
__device__ float g_y23[NC];

__device__ __forceinline__ float sigmoidf_(float x) {
    return 1.0f / (1.0f + __expf(-x));
}

// ---------------- pack: Wcat + concat(slot,value) --------------------------
__global__ void pack_kernel(const float* __restrict__ w1,
                            const float* __restrict__ w2,
                            const float* __restrict__ w3,
                            const float* __restrict__ slot,
                            const float* __restrict__ val) {
    int i = blockIdx.x * blockDim.x + threadIdx.x;
    if (i < 1800 * 300) {
        int n = i / 300, c = i % 300;
        int g = n / 300, f = n % 300;
        float v;
        if      (g == 0) v = w1[f * 300 + c];            // w1[f,c,0]
        else if (g == 1) v = w2[(f * 300 + c) * 2 + 0];  // w2[f,c,0]
        else if (g == 2) v = w2[(f * 300 + c) * 2 + 1];  // w2[f,c,1]
        else if (g == 3) v = w3[(f * 300 + c) * 3 + 0];
        else if (g == 4) v = w3[(f * 300 + c) * 3 + 1];
        else             v = w3[(f * 300 + c) * 3 + 2];
        g_Wcat[i] = v;
    }
    if (i < 1000 * 600) {
        int c = i / 600, k = i % 600;
        g_catSV[i] = (k < 300) ? slot[c * 300 + k] : val[c * 300 + (k - 300)];
    }
}

// ---------------- generic NT SGEMM: C = act(A@B^T + bias) [* mul_src] ------
// A: [M,K] row-major (lda), B: [N,K] row-major (ldb), C: [M,N] (ldc)
template <int BM, int BN, int BK, int TM, int TN>
__global__ void sgemm_nt(const float* __restrict__ A, int lda,
                         const float* __restrict__ Bm, int ldb,
                         float* __restrict__ Cm, int ldc,
                         int M, int N, int K,
                         const float* __restrict__ bias, int act,
                         const float* __restrict__ mul_src) {
    __shared__ float As[BK][BM];
    __shared__ float Bs[BK][BN];
    const int tid = threadIdx.x;
    const int nTx = BN / TN;
    const int tx = tid % nTx;
    const int ty = tid / nTx;
    const int m0 = blockIdx.y * BM;
    const int n0 = blockIdx.x * BN;

    float acc[TM][TN];
#pragma unroll
    for (int i = 0; i < TM; i++)
#pragma unroll
        for (int j = 0; j < TN; j++) acc[i][j] = 0.f;

    for (int k0 = 0; k0 < K; k0 += BK) {
        for (int e = tid; e < BM * BK; e += blockDim.x) {
            int r = e / BK, c = e % BK;
            int gm = m0 + r, gk = k0 + c;
            As[c][r] = (gm < M && gk < K) ? A[gm * lda + gk] : 0.f;
        }
        for (int e = tid; e < BN * BK; e += blockDim.x) {
            int r = e / BK, c = e % BK;
            int gn = n0 + r, gk = k0 + c;
            Bs[c][r] = (gn < N && gk < K) ? Bm[gn * ldb + gk] : 0.f;
        }
        __syncthreads();
#pragma unroll
        for (int k = 0; k < BK; k++) {
            float a[TM], b[TN];
#pragma unroll
            for (int i = 0; i < TM; i++) a[i] = As[k][ty * TM + i];
#pragma unroll
            for (int j = 0; j < TN; j++) b[j] = Bs[k][tx * TN + j];
#pragma unroll
            for (int i = 0; i < TM; i++)
#pragma unroll
                for (int j = 0; j < TN; j++) acc[i][j] += a[i] * b[j];
        }
        __syncthreads();
    }

#pragma unroll
    for (int i = 0; i < TM; i++) {
        int gm = m0 + ty * TM + i;
        if (gm >= M) continue;
#pragma unroll
        for (int j = 0; j < TN; j++) {
            int gn = n0 + tx * TN + j;
            if (gn >= N) continue;
            float v = acc[i][j];
            if (bias) v += bias[gn];
            if (act) v = sigmoidf_(v);
            if (mul_src) v *= mul_src[gm * ldc + gn];
            Cm[gm * ldc + gn] = v;
        }
    }
}

// ---------------- conv combine: shift-add, relu, maxpool over time ---------
__global__ void pool_kernel(const float* __restrict__ b1,
                            const float* __restrict__ b2,
                            const float* __restrict__ b3) {
    int b = blockIdx.x;
    int f = threadIdx.x;
    if (f >= ND) return;
    const float* Gb = g_G + (size_t)b * NL * 1800;
    float m1 = -1e30f, m2 = -1e30f, m3 = -1e30f;
    for (int t = 0; t < NL; t++)
        m1 = fmaxf(m1, Gb[t * 1800 + f]);
    for (int t = 0; t < NL - 1; t++)
        m2 = fmaxf(m2, Gb[t * 1800 + 300 + f] + Gb[(t + 1) * 1800 + 600 + f]);
    for (int t = 0; t < NL - 2; t++)
        m3 = fmaxf(m3, Gb[t * 1800 + 900 + f] + Gb[(t + 1) * 1800 + 1200 + f]
                       + Gb[(t + 2) * 1800 + 1500 + f]);
    float v = fmaxf(m1 + b1[f], 0.f) + fmaxf(m2 + b2[f], 0.f) + fmaxf(m3 + b3[f], 0.f);
    g_fu[b * ND + f] = v;
    g_fuT[f * NB + b] = v;
}

// ---------------- y2+y3 per candidate --------------------------------------
__global__ void y23_kernel(const float* __restrict__ Wmr, const float* __restrict__ bmr,
                           const float* __restrict__ Wmc, const float* __restrict__ bmc,
                           const float* __restrict__ Wj, const float* __restrict__ bj) {
    int c = blockIdx.x;
    __shared__ float sr[ND], sc[ND];
    __shared__ float red[128];
    int t = threadIdx.x;  // 128
    for (int d = t; d < ND; d += 128) {
        sr[d] = sigmoidf_(g_mr[c * ND + d]);
        sc[d] = sigmoidf_(g_mc[c * ND + d]);
    }
    __syncthreads();
    float y = 0.f;
    for (int h = t; h < NH; h += 128) {
        float ar = bmr[h], ac = bmc[h];
        for (int d = 0; d < ND; d++) {
            ar += Wmr[h * ND + d] * sr[d];
            ac += Wmc[h * ND + d] * sc[d];
        }
        y += Wj[h] * (sigmoidf_(ar) + sigmoidf_(ac));
    }
    red[t] = y;
    __syncthreads();
    for (int s = 64; s > 0; s >>= 1) {
        if (t < s) red[t] += red[t + s];
        __syncthreads();
    }
    if (t == 0) g_y23[c] = red[0] + 2.f * bj[0];
}

// ---------------- big fused y1 + output -------------------------------------
// block: 64 candidates x (H padded to 128) for one batch b.
// A[m,k] = sigmoid(cand[c0+m,k] * fu[b,k]) computed on the fly.
__global__ void final_kernel(const float* __restrict__ Wd, const float* __restrict__ bd,
                             const float* __restrict__ Wj, const float* __restrict__ bj,
                             const float* __restrict__ ypast, float* __restrict__ out) {
    const int c0 = blockIdx.x * 64;
    const int b = blockIdx.y;
    __shared__ float fu_s[ND];
    __shared__ float As[16][64];
    __shared__ float Bs[16][128];
    __shared__ float red[64][17];
    const int tid = threadIdx.x;  // 256
    const int tx = tid % 16, ty = tid / 16;

    for (int i = tid; i < ND; i += 256) fu_s[i] = g_fu[b * ND + i];
    __syncthreads();

    float acc[4][8];
#pragma unroll
    for (int i = 0; i < 4; i++)
#pragma unroll
        for (int j = 0; j < 8; j++) acc[i][j] = 0.f;

    for (int k0 = 0; k0 < ND; k0 += 16) {
        for (int e = tid; e < 64 * 16; e += 256) {
            int r = e / 16, cc = e % 16;
            int gc = c0 + r, gk = k0 + cc;
            float v = 0.f;
            if (gc < NC && gk < ND) v = sigmoidf_(g_cand[gc * ND + gk] * fu_s[gk]);
            As[cc][r] = v;
        }
        for (int e = tid; e < 128 * 16; e += 256) {
            int r = e / 16, cc = e % 16;
            int gk = k0 + cc;
            Bs[cc][r] = (r < NH && gk < ND) ? Wd[r * ND + gk] : 0.f;
        }
        __syncthreads();
#pragma unroll
        for (int k = 0; k < 16; k++) {
            float a[4], bb[8];
#pragma unroll
            for (int i = 0; i < 4; i++) a[i] = As[k][ty * 4 + i];
#pragma unroll
            for (int j = 0; j < 8; j++) bb[j] = Bs[k][tx * 8 + j];
#pragma unroll
            for (int i = 0; i < 4; i++)
#pragma unroll
                for (int j = 0; j < 8; j++) acc[i][j] += a[i] * bb[j];
        }
        __syncthreads();
    }

    // epilogue: sigmoid -> Wj dot (partial over this thread's 8 h-cols)
#pragma unroll
    for (int i = 0; i < 4; i++) {
        float p = 0.f;
#pragma unroll
        for (int j = 0; j < 8; j++) {
            int h = tx * 8 + j;
            if (h < NH) p += Wj[h] * sigmoidf_(bd[h] + acc[i][j]);
        }
        red[ty * 4 + i][tx] = p;
    }
    __syncthreads();
    if (tid < 64) {
        float s = 0.f;
#pragma unroll
        for (int q = 0; q < 16; q++) s += red[tid][q];
        int gc = c0 + tid;
        if (gc < NC) {
            float tot = bj[0] + s + g_y23[gc];
            out[b * NC + gc] = 0.5f * tot + 0.5f * ypast[b * NC + gc];
        }
    }
}

// ---------------- launch -----------------------------------------------------
extern "C" void kernel_launch(void* const* d_in, const int* in_sizes, int n_in,
                              void* d_out, int out_size) {
    const float* utt      = (const float*)d_in[0];
    const float* sys_s    = (const float*)d_in[1];
    const float* conf_s   = (const float*)d_in[2];
    const float* conf_v   = (const float*)d_in[3];
    const float* ypast    = (const float*)d_in[4];
    const float* slot_emb = (const float*)d_in[5];
    const float* val_emb  = (const float*)d_in[6];
    const float* Wc       = (const float*)d_in[7];
    const float* bc       = (const float*)d_in[8];
    const float* cw1      = (const float*)d_in[9];
    const float* cb1      = (const float*)d_in[10];
    const float* cw2      = (const float*)d_in[11];
    const float* cb2      = (const float*)d_in[12];
    const float* cw3      = (const float*)d_in[13];
    const float* cb3      = (const float*)d_in[14];
    const float* Wd       = (const float*)d_in[15];
    const float* bd       = (const float*)d_in[16];
    const float* Wmr      = (const float*)d_in[17];
    const float* bmr      = (const float*)d_in[18];
    const float* Wmc      = (const float*)d_in[19];
    const float* bmc      = (const float*)d_in[20];
    const float* Wj       = (const float*)d_in[21];
    const float* bj       = (const float*)d_in[22];
    float* out = (float*)d_out;
    (void)in_sizes; (void)n_in; (void)out_size;

    // Resolve REAL device addresses of the scratch globals. Taking the symbol
    // address directly in host code yields the host shadow (which GB300's ATS
    // happily dereferences over C2C — the round-3 bug). cudaGetSymbolAddress
    // is a pure query: no allocation, graph-capture safe.
    float *p_Wcat, *p_catSV, *p_G, *p_fuT, *p_cand, *p_P, *p_Q, *p_mr, *p_mc;
    cudaGetSymbolAddress((void**)&p_Wcat,  g_Wcat);
    cudaGetSymbolAddress((void**)&p_catSV, g_catSV);
    cudaGetSymbolAddress((void**)&p_G,     g_G);
    cudaGetSymbolAddress((void**)&p_fuT,   g_fuT);
    cudaGetSymbolAddress((void**)&p_cand,  g_cand);
    cudaGetSymbolAddress((void**)&p_P,     g_P);
    cudaGetSymbolAddress((void**)&p_Q,     g_Q);
    cudaGetSymbolAddress((void**)&p_mr,    g_mr);
    cudaGetSymbolAddress((void**)&p_mc,    g_mc);

    // 1. pack Wcat + concat(slot,value)
    pack_kernel<<<(600000 + 255) / 256, 256>>>(cw1, cw2, cw3, slot_emb, val_emb);

    // 2. conv GEMM: G[5120,1800] = utt[5120,300] @ Wcat^T
    {
        dim3 grid((1800 + 127) / 128, (5120 + 127) / 128);
        sgemm_nt<128, 128, 16, 8, 8><<<grid, 256>>>(
            utt, 300, p_Wcat, 300, p_G, 1800,
            5120, 1800, 300, nullptr, 0, nullptr);
    }

    // 3. combine + pool -> fu, fuT
    pool_kernel<<<NB, 320>>>(cb1, cb2, cb3);

    // 4. cand = sigmoid(catSV @ Wc^T + bc)
    {
        dim3 grid((300 + 63) / 64, (1000 + 63) / 64);
        sgemm_nt<64, 64, 16, 4, 4><<<grid, 256>>>(
            p_catSV, 600, Wc, 600, p_cand, 300,
            NC, ND, 600, bc, 1, nullptr);
    }

    // 5-7. P = slot@sys^T ; Q = (slot@conf_s^T) * (val@conf_v^T)
    {
        dim3 grid((128 + 63) / 64, (1000 + 63) / 64);
        sgemm_nt<64, 64, 16, 4, 4><<<grid, 256>>>(
            slot_emb, 300, sys_s, 300, p_P, 128,
            NC, NB, 300, nullptr, 0, nullptr);
        sgemm_nt<64, 64, 16, 4, 4><<<grid, 256>>>(
            slot_emb, 300, conf_s, 300, p_Q, 128,
            NC, NB, 300, nullptr, 0, nullptr);
        sgemm_nt<64, 64, 16, 4, 4><<<grid, 256>>>(
            val_emb, 300, conf_v, 300, p_Q, 128,
            NC, NB, 300, nullptr, 0, p_Q);
    }

    // 8/9. m_r = P @ fu, m_c = Q @ fu   (via fuT as NT)
    {
        dim3 grid((300 + 63) / 64, (1000 + 63) / 64);
        sgemm_nt<64, 64, 16, 4, 4><<<grid, 256>>>(
            p_P, 128, p_fuT, 128, p_mr, 300,
            NC, ND, 128, nullptr, 0, nullptr);
        sgemm_nt<64, 64, 16, 4, 4><<<grid, 256>>>(
            p_Q, 128, p_fuT, 128, p_mc, 300,
            NC, ND, 128, nullptr, 0, nullptr);
    }

    // 10. y23
    y23_kernel<<<NC, 128>>>(Wmr, bmr, Wmc, bmc, Wj, bj);

    // 11. fused y1 + combine + output
    {
        dim3 grid((NC + 63) / 64, NB);
        final_kernel<<<grid, 256>>>(Wd, bd, Wj, bj, ypast, out);
    }
}

// round 8
// speedup vs baseline: 1.5502x; 1.5502x over previous
#include <cuda_runtime.h>
#include <math.h>

#define NB 128
#define NC 1000
#define ND 300
#define NL 40
#define NH 100

// ---------------- scratch (device globals; no allocation allowed) ----------
__device__ float g_Wcat[1800 * 300];      // stacked conv weights [6D, D]
__device__ float g_catSV[1000 * 600];     // concat(slot_emb, value_emb)
__device__ float g_WmrT[ND * NH];         // Wmr transposed [D, H]
__device__ float g_WmcT[ND * NH];         // Wmc transposed [D, H]
__device__ float g_G[5120 * 1800];        // conv pre-activations, [B*L, 6D]
__device__ float g_fu[NB * ND];           // final_utt [B, D]
__device__ float g_cand[NC * ND];         // sigmoid(candidates transform)
__device__ float g_P[NC * NB];            // slot_emb @ sys_slots^T
__device__ float g_Q[NC * NB];            // (slot@conf_s^T)*(value@conf_v^T)
__device__ float g_y23[NC];

__device__ __forceinline__ float sigmoidf_(float x) {
    return 1.0f / (1.0f + __expf(-x));
}

// ---------------- pack: Wcat + concat(slot,value) + WmT transposes ---------
__global__ void pack_kernel(const float* __restrict__ w1,
                            const float* __restrict__ w2,
                            const float* __restrict__ w3,
                            const float* __restrict__ slot,
                            const float* __restrict__ val,
                            const float* __restrict__ Wmr,
                            const float* __restrict__ Wmc) {
    int i = blockIdx.x * blockDim.x + threadIdx.x;
    if (i < 1800 * 300) {
        int n = i / 300, c = i % 300;
        int g = n / 300, f = n % 300;
        float v;
        if      (g == 0) v = w1[f * 300 + c];
        else if (g == 1) v = w2[(f * 300 + c) * 2 + 0];
        else if (g == 2) v = w2[(f * 300 + c) * 2 + 1];
        else if (g == 3) v = w3[(f * 300 + c) * 3 + 0];
        else if (g == 4) v = w3[(f * 300 + c) * 3 + 1];
        else             v = w3[(f * 300 + c) * 3 + 2];
        g_Wcat[i] = v;
    }
    if (i < 1000 * 600) {
        int c = i / 600, k = i % 600;
        g_catSV[i] = (k < 300) ? slot[c * 300 + k] : val[c * 300 + (k - 300)];
    }
    if (i < ND * NH) {
        int d = i / NH, h = i % NH;
        g_WmrT[i] = Wmr[h * ND + d];
        g_WmcT[i] = Wmc[h * ND + d];
    }
}

// ---------------- double-buffered NT SGEMM: C = act(A@B^T + bias) ----------
// A: [M,K] row-major (lda), B: [N,K] row-major (ldb), C: [M,N] (ldc)
// blockDim must be 256.
template <int BM, int BN, int BK, int TM, int TN>
__global__ void sgemm_db(const float* __restrict__ A, int lda,
                         const float* __restrict__ Bm, int ldb,
                         float* __restrict__ Cm, int ldc,
                         int M, int N, int K,
                         const float* __restrict__ bias, int act) {
    constexpr int THREADS = 256;
    constexpr int EA = BM * BK / THREADS;
    constexpr int EB = BN * BK / THREADS;
    __shared__ float As[2][BK][BM];
    __shared__ float Bs[2][BK][BN];
    const int tid = threadIdx.x;
    const int nTx = BN / TN;
    const int tx = tid % nTx;
    const int ty = tid / nTx;
    const int m0 = blockIdx.y * BM;
    const int n0 = blockIdx.x * BN;
    const int nt = (K + BK - 1) / BK;

    float rA[EA], rB[EB];
    float acc[TM][TN];
#pragma unroll
    for (int i = 0; i < TM; i++)
#pragma unroll
        for (int j = 0; j < TN; j++) acc[i][j] = 0.f;

    // prologue: load tile 0 into regs, store to buf 0
#pragma unroll
    for (int u = 0; u < EA; u++) {
        int e = tid + u * THREADS;
        int r = e / BK, c = e % BK;
        int gm = m0 + r, gk = c;
        rA[u] = (gm < M && gk < K) ? A[gm * lda + gk] : 0.f;
    }
#pragma unroll
    for (int u = 0; u < EB; u++) {
        int e = tid + u * THREADS;
        int r = e / BK, c = e % BK;
        int gn = n0 + r, gk = c;
        rB[u] = (gn < N && gk < K) ? Bm[gn * ldb + gk] : 0.f;
    }
    int buf = 0;
#pragma unroll
    for (int u = 0; u < EA; u++) {
        int e = tid + u * THREADS;
        As[0][e % BK][e / BK] = rA[u];
    }
#pragma unroll
    for (int u = 0; u < EB; u++) {
        int e = tid + u * THREADS;
        Bs[0][e % BK][e / BK] = rB[u];
    }
    __syncthreads();

    for (int kt = 0; kt < nt; kt++) {
        if (kt + 1 < nt) {
            int k0 = (kt + 1) * BK;
#pragma unroll
            for (int u = 0; u < EA; u++) {
                int e = tid + u * THREADS;
                int r = e / BK, c = e % BK;
                int gm = m0 + r, gk = k0 + c;
                rA[u] = (gm < M && gk < K) ? A[gm * lda + gk] : 0.f;
            }
#pragma unroll
            for (int u = 0; u < EB; u++) {
                int e = tid + u * THREADS;
                int r = e / BK, c = e % BK;
                int gn = n0 + r, gk = k0 + c;
                rB[u] = (gn < N && gk < K) ? Bm[gn * ldb + gk] : 0.f;
            }
        }
#pragma unroll
        for (int k = 0; k < BK; k++) {
            float a[TM], b[TN];
#pragma unroll
            for (int i = 0; i < TM; i++) a[i] = As[buf][k][ty * TM + i];
#pragma unroll
            for (int j = 0; j < TN; j++) b[j] = Bs[buf][k][tx * TN + j];
#pragma unroll
            for (int i = 0; i < TM; i++)
#pragma unroll
                for (int j = 0; j < TN; j++) acc[i][j] += a[i] * b[j];
        }
        if (kt + 1 < nt) {
            int nb = buf ^ 1;
#pragma unroll
            for (int u = 0; u < EA; u++) {
                int e = tid + u * THREADS;
                As[nb][e % BK][e / BK] = rA[u];
            }
#pragma unroll
            for (int u = 0; u < EB; u++) {
                int e = tid + u * THREADS;
                Bs[nb][e % BK][e / BK] = rB[u];
            }
            __syncthreads();
            buf = nb;
        }
    }

#pragma unroll
    for (int i = 0; i < TM; i++) {
        int gm = m0 + ty * TM + i;
        if (gm >= M) continue;
#pragma unroll
        for (int j = 0; j < TN; j++) {
            int gn = n0 + tx * TN + j;
            if (gn >= N) continue;
            float v = acc[i][j];
            if (bias) v += bias[gn];
            if (act) v = sigmoidf_(v);
            Cm[gm * ldc + gn] = v;
        }
    }
}

// ---------------- conv combine: shift-add, relu, maxpool over time ---------
__global__ void pool_kernel(const float* __restrict__ b1,
                            const float* __restrict__ b2,
                            const float* __restrict__ b3) {
    int b = blockIdx.x;
    int f = threadIdx.x;
    if (f >= ND) return;
    const float* Gb = g_G + (size_t)b * NL * 1800;
    float m1 = -1e30f, m2 = -1e30f, m3 = -1e30f;
    for (int t = 0; t < NL; t++)
        m1 = fmaxf(m1, Gb[t * 1800 + f]);
    for (int t = 0; t < NL - 1; t++)
        m2 = fmaxf(m2, Gb[t * 1800 + 300 + f] + Gb[(t + 1) * 1800 + 600 + f]);
    for (int t = 0; t < NL - 2; t++)
        m3 = fmaxf(m3, Gb[t * 1800 + 900 + f] + Gb[(t + 1) * 1800 + 1200 + f]
                       + Gb[(t + 2) * 1800 + 1500 + f]);
    float v = fmaxf(m1 + b1[f], 0.f) + fmaxf(m2 + b2[f], 0.f) + fmaxf(m3 + b3[f], 0.f);
    g_fu[b * ND + f] = v;
}

// ---------------- fused P & Q: 3 GEMMs sharing tiles ------------------------
// P = slot @ sys^T ; Q = (slot @ conf_s^T) * (val @ conf_v^T)   [NC, NB]
__global__ void pq_kernel(const float* __restrict__ slot,
                          const float* __restrict__ val,
                          const float* __restrict__ sys_s,
                          const float* __restrict__ conf_s,
                          const float* __restrict__ conf_v) {
    constexpr int BM = 64, BN = 64, BK = 16, TM = 4, TN = 4;
    __shared__ float Ss[BK][BM], Vs[BK][BM];
    __shared__ float By[BK][BN], Bc[BK][BN], Bv[BK][BN];
    const int tid = threadIdx.x;  // 256
    const int nTx = BN / TN;
    const int tx = tid % nTx, ty = tid / nTx;
    const int m0 = blockIdx.y * BM;
    const int n0 = blockIdx.x * BN;

    float aP[TM][TN], a1[TM][TN], a2[TM][TN];
#pragma unroll
    for (int i = 0; i < TM; i++)
#pragma unroll
        for (int j = 0; j < TN; j++) { aP[i][j] = 0.f; a1[i][j] = 0.f; a2[i][j] = 0.f; }

    for (int k0 = 0; k0 < ND; k0 += BK) {
        for (int e = tid; e < BM * BK; e += 256) {
            int r = e / BK, c = e % BK;
            int gm = m0 + r, gk = k0 + c;
            float s = 0.f, v = 0.f;
            if (gm < NC && gk < ND) { s = slot[gm * ND + gk]; v = val[gm * ND + gk]; }
            Ss[c][r] = s; Vs[c][r] = v;
        }
        for (int e = tid; e < BN * BK; e += 256) {
            int r = e / BK, c = e % BK;
            int gn = n0 + r, gk = k0 + c;
            float y = 0.f, cs = 0.f, cv = 0.f;
            if (gk < ND) {
                y  = sys_s[gn * ND + gk];
                cs = conf_s[gn * ND + gk];
                cv = conf_v[gn * ND + gk];
            }
            By[c][r] = y; Bc[c][r] = cs; Bv[c][r] = cv;
        }
        __syncthreads();
#pragma unroll
        for (int k = 0; k < BK; k++) {
            float s[TM], v[TM], by[TN], bc[TN], bv[TN];
#pragma unroll
            for (int i = 0; i < TM; i++) { s[i] = Ss[k][ty * TM + i]; v[i] = Vs[k][ty * TM + i]; }
#pragma unroll
            for (int j = 0; j < TN; j++) { by[j] = By[k][tx * TN + j]; bc[j] = Bc[k][tx * TN + j]; bv[j] = Bv[k][tx * TN + j]; }
#pragma unroll
            for (int i = 0; i < TM; i++)
#pragma unroll
                for (int j = 0; j < TN; j++) {
                    aP[i][j] += s[i] * by[j];
                    a1[i][j] += s[i] * bc[j];
                    a2[i][j] += v[i] * bv[j];
                }
        }
        __syncthreads();
    }

#pragma unroll
    for (int i = 0; i < TM; i++) {
        int gm = m0 + ty * TM + i;
        if (gm >= NC) continue;
#pragma unroll
        for (int j = 0; j < TN; j++) {
            int gn = n0 + tx * TN + j;  // always < 128
            g_P[gm * NB + gn] = aP[i][j];
            g_Q[gm * NB + gn] = a1[i][j] * a2[i][j];
        }
    }
}

// ---------------- fused gates: m_r, m_c, y2+y3 in one kernel ----------------
// block = 4 candidates, 384 threads.
__global__ void gates_kernel(const float* __restrict__ bmr,
                             const float* __restrict__ bmc,
                             const float* __restrict__ Wj,
                             const float* __restrict__ bj) {
    const int c0 = blockIdx.x * 4;
    __shared__ __align__(16) float Pr[NB][4];
    __shared__ __align__(16) float Qr[NB][4];
    __shared__ __align__(16) float sA[2][ND][4];  // [0]=sigmoid(m_r), [1]=sigmoid(m_c)
    __shared__ float red[200][4];
    const int t = threadIdx.x;  // 384

    for (int e = t; e < 4 * NB; e += 384) {
        int bb = e >> 2, ci = e & 3;
        Pr[bb][ci] = g_P[(c0 + ci) * NB + bb];
        Qr[bb][ci] = g_Q[(c0 + ci) * NB + bb];
    }
    __syncthreads();

    // stage A: m_r[c,d] = sum_b P[c,b] fu[b,d]; same for m_c with Q. thread = d.
    if (t < ND) {
        float ar[4] = {0.f, 0.f, 0.f, 0.f};
        float ac[4] = {0.f, 0.f, 0.f, 0.f};
        for (int b = 0; b < NB; b++) {
            float f = g_fu[b * ND + t];
            float4 p = *(const float4*)&Pr[b][0];
            float4 q = *(const float4*)&Qr[b][0];
            ar[0] += p.x * f; ar[1] += p.y * f; ar[2] += p.z * f; ar[3] += p.w * f;
            ac[0] += q.x * f; ac[1] += q.y * f; ac[2] += q.z * f; ac[3] += q.w * f;
        }
#pragma unroll
        for (int ci = 0; ci < 4; ci++) {
            sA[0][t][ci] = sigmoidf_(ar[ci]);
            sA[1][t][ci] = sigmoidf_(ac[ci]);
        }
    }
    __syncthreads();

    // stage B: a[h] = bm[h] + sum_d WmT[d,h] * s[d]; partial = Wj[h]*sigmoid(a)
    if (t < 2 * NH) {
        int which = t / NH, h = t % NH;
        const float* WmT = which ? g_WmcT : g_WmrT;
        float bb = which ? bmc[h] : bmr[h];
        float a[4] = {bb, bb, bb, bb};
        for (int d = 0; d < ND; d++) {
            float w = WmT[d * NH + h];
            float4 s = *(const float4*)&sA[which][d][0];
            a[0] += w * s.x; a[1] += w * s.y; a[2] += w * s.z; a[3] += w * s.w;
        }
        float wj = Wj[h];
#pragma unroll
        for (int ci = 0; ci < 4; ci++) red[t][ci] = wj * sigmoidf_(a[ci]);
    }
    __syncthreads();

    if (t < 4) {
        float s = 0.f;
        for (int e = 0; e < 2 * NH; e++) s += red[e][t];
        g_y23[c0 + t] = s + 2.f * bj[0];  // y2's bj + y3's bj
    }
}

// ---------------- big fused y1 + output (exact H=100 tile) ------------------
// block: 64 candidates x 100 H for one batch b; 320 threads, 4x5 micro-tile.
__global__ void final_kernel(const float* __restrict__ Wd, const float* __restrict__ bd,
                             const float* __restrict__ Wj, const float* __restrict__ bj,
                             const float* __restrict__ ypast, float* __restrict__ out) {
    const int c0 = blockIdx.x * 64;
    const int b = blockIdx.y;
    __shared__ float fu_s[ND];
    __shared__ float As[16][64];
    __shared__ float Bs[16][100];
    __shared__ float red[64][20];
    const int tid = threadIdx.x;  // 320
    const int tx = tid % 20, ty = tid / 20;  // tx: 0..19 (h-groups of 5), ty: 0..15

    for (int i = tid; i < ND; i += 320) fu_s[i] = g_fu[b * ND + i];
    __syncthreads();

    float acc[4][5];
#pragma unroll
    for (int i = 0; i < 4; i++)
#pragma unroll
        for (int j = 0; j < 5; j++) acc[i][j] = 0.f;

    for (int k0 = 0; k0 < ND; k0 += 16) {
        for (int e = tid; e < 64 * 16; e += 320) {
            int r = e / 16, cc = e % 16;
            int gc = c0 + r, gk = k0 + cc;
            float v = 0.f;
            if (gc < NC && gk < ND) v = sigmoidf_(g_cand[gc * ND + gk] * fu_s[gk]);
            As[cc][r] = v;
        }
        for (int e = tid; e < 100 * 16; e += 320) {
            int r = e / 16, cc = e % 16;
            int gk = k0 + cc;
            Bs[cc][r] = (gk < ND) ? Wd[r * ND + gk] : 0.f;
        }
        __syncthreads();
#pragma unroll
        for (int k = 0; k < 16; k++) {
            float a[4], w[5];
#pragma unroll
            for (int i = 0; i < 4; i++) a[i] = As[k][ty * 4 + i];
#pragma unroll
            for (int j = 0; j < 5; j++) w[j] = Bs[k][tx * 5 + j];
#pragma unroll
            for (int i = 0; i < 4; i++)
#pragma unroll
                for (int j = 0; j < 5; j++) acc[i][j] += a[i] * w[j];
        }
        __syncthreads();
    }

    // epilogue: sigmoid -> Wj dot (partial over this thread's 5 h-cols)
#pragma unroll
    for (int i = 0; i < 4; i++) {
        float p = 0.f;
#pragma unroll
        for (int j = 0; j < 5; j++) {
            int h = tx * 5 + j;  // always < 100
            p += Wj[h] * sigmoidf_(bd[h] + acc[i][j]);
        }
        red[ty * 4 + i][tx] = p;
    }
    __syncthreads();
    if (tid < 64) {
        float s = 0.f;
#pragma unroll
        for (int q = 0; q < 20; q++) s += red[tid][q];
        int gc = c0 + tid;
        if (gc < NC) {
            float tot = bj[0] + s + g_y23[gc];
            out[b * NC + gc] = 0.5f * tot + 0.5f * ypast[b * NC + gc];
        }
    }
}

// ---------------- launch -----------------------------------------------------
extern "C" void kernel_launch(void* const* d_in, const int* in_sizes, int n_in,
                              void* d_out, int out_size) {
    const float* utt      = (const float*)d_in[0];
    const float* sys_s    = (const float*)d_in[1];
    const float* conf_s   = (const float*)d_in[2];
    const float* conf_v   = (const float*)d_in[3];
    const float* ypast    = (const float*)d_in[4];
    const float* slot_emb = (const float*)d_in[5];
    const float* val_emb  = (const float*)d_in[6];
    const float* Wc       = (const float*)d_in[7];
    const float* bc       = (const float*)d_in[8];
    const float* cw1      = (const float*)d_in[9];
    const float* cb1      = (const float*)d_in[10];
    const float* cw2      = (const float*)d_in[11];
    const float* cb2      = (const float*)d_in[12];
    const float* cw3      = (const float*)d_in[13];
    const float* cb3      = (const float*)d_in[14];
    const float* Wd       = (const float*)d_in[15];
    const float* bd       = (const float*)d_in[16];
    const float* Wmr      = (const float*)d_in[17];
    const float* bmr      = (const float*)d_in[18];
    const float* Wmc      = (const float*)d_in[19];
    const float* bmc      = (const float*)d_in[20];
    const float* Wj       = (const float*)d_in[21];
    const float* bj       = (const float*)d_in[22];
    float* out = (float*)d_out;
    (void)in_sizes; (void)n_in; (void)out_size;

    // Resolve REAL device addresses of scratch globals (host-shadow trap on ATS).
    float *p_Wcat, *p_catSV, *p_G, *p_cand;
    cudaGetSymbolAddress((void**)&p_Wcat,  g_Wcat);
    cudaGetSymbolAddress((void**)&p_catSV, g_catSV);
    cudaGetSymbolAddress((void**)&p_G,     g_G);
    cudaGetSymbolAddress((void**)&p_cand,  g_cand);

    // 1. pack Wcat + concat(slot,value) + WmT transposes
    pack_kernel<<<(600000 + 255) / 256, 256>>>(cw1, cw2, cw3, slot_emb, val_emb, Wmr, Wmc);

    // 2. conv GEMM: G[5120,1800] = utt[5120,300] @ Wcat^T  (double-buffered)
    {
        dim3 grid((1800 + 127) / 128, (5120 + 127) / 128);
        sgemm_db<128, 128, 16, 8, 8><<<grid, 256>>>(
            utt, 300, p_Wcat, 300, p_G, 1800,
            5120, 1800, 300, nullptr, 0);
    }

    // 3. combine + pool -> fu
    pool_kernel<<<NB, 320>>>(cb1, cb2, cb3);

    // 4. cand = sigmoid(catSV @ Wc^T + bc)  (double-buffered)
    {
        dim3 grid((300 + 63) / 64, (1000 + 63) / 64);
        sgemm_db<64, 64, 16, 4, 4><<<grid, 256>>>(
            p_catSV, 600, Wc, 600, p_cand, 300,
            NC, ND, 600, bc, 1);
    }

    // 5. fused P & Q
    {
        dim3 grid(2, 16);
        pq_kernel<<<grid, 256>>>(slot_emb, val_emb, sys_s, conf_s, conf_v);
    }

    // 6. fused gates (m_r, m_c, y2+y3)
    gates_kernel<<<NC / 4, 384>>>(bmr, bmc, Wj, bj);

    // 7. fused y1 + combine + output
    {
        dim3 grid((NC + 63) / 64, NB);
        final_kernel<<<grid, 320>>>(Wd, bd, Wj, bj, ypast, out);
    }
}

// round 14
// speedup vs baseline: 1.7497x; 1.1287x over previous
#include <cuda_runtime.h>
#include <cuda_bf16.h>
#include <mma.h>
#include <math.h>
#include <stdint.h>

using namespace nvcuda;

#define NB 128
#define NC 1000
#define ND 300
#define NL 40
#define NH 100

#define KP300 320     // K=300 padded to 10 chunks of 32
#define KP600 608     // K=600 padded to 19 chunks of 32
#define GLD   1920    // g_G column pad (15 n-tiles of 128)

// ---------------- scratch (device globals; zero-initialized, no alloc) -----
__device__ __align__(16) float g_WcatF[1800 * 300];
__device__ __align__(16) __nv_bfloat16 g_utt_h[5120 * KP300],  g_utt_l[5120 * KP300];
__device__ __align__(16) __nv_bfloat16 g_Wcat_h[1920 * KP300], g_Wcat_l[1920 * KP300];
__device__ __align__(16) __nv_bfloat16 g_catSV_h[1024 * KP600], g_catSV_l[1024 * KP600];
__device__ __align__(16) __nv_bfloat16 g_Wc_h[384 * KP600],    g_Wc_l[384 * KP600];
__device__ __align__(16) __nv_bfloat16 g_slot_h[1024 * KP300], g_slot_l[1024 * KP300];
__device__ __align__(16) __nv_bfloat16 g_val_h[1024 * KP300],  g_val_l[1024 * KP300];
__device__ __align__(16) __nv_bfloat16 g_B3_h[384 * KP300],    g_B3_l[384 * KP300];
__device__ __align__(16) __nv_bfloat16 g_Wd_h[128 * KP300],    g_Wd_l[128 * KP300];
__device__ __align__(16) float g_G[5120 * GLD];     // conv pre-act, col-padded
__device__ __align__(16) float g_fu[NB * ND];
__device__ __align__(16) float g_cand[NC * ND];
__device__ __align__(16) float g_PTT[1024 * 384];   // [P | T1 | T2]
__device__ __align__(16) float g_WmrT[ND * NH];
__device__ __align__(16) float g_WmcT[ND * NH];
__device__ float g_y23[NC];

__device__ __forceinline__ float sigmoidf_(float x) {
    return 1.0f / (1.0f + __expf(-x));
}

__device__ __forceinline__ void split_bf(float x, __nv_bfloat16& h, __nv_bfloat16& l) {
    h = __float2bfloat16_rn(x);
    l = __float2bfloat16_rn(x - __bfloat162float(h));
}

__device__ __forceinline__ uint32_t pack_bf(__nv_bfloat16 a, __nv_bfloat16 b) {
    return (uint32_t)__bfloat16_as_ushort(a) | ((uint32_t)__bfloat16_as_ushort(b) << 16);
}

// ---------------- presplit: fp32 [M,K] -> bf16 hi/lo [*,Kpad] ---------------
__global__ void presplit_kernel(const float* __restrict__ src, int M, int K,
                                __nv_bfloat16* __restrict__ dh,
                                __nv_bfloat16* __restrict__ dl,
                                int Kpad, int rowoff, int coloff) {
    int i = blockIdx.x * blockDim.x + threadIdx.x;
    if (i >= M * K) return;
    int r = i / K, c = i % K;
    float x = src[i];
    __nv_bfloat16 h, l;
    split_bf(x, h, l);
    size_t o = (size_t)(rowoff + r) * Kpad + coloff + c;
    dh[o] = h; dl[o] = l;
}

// ---------------- pack: Wcat fp32 + WmT transposes --------------------------
__global__ void pack_kernel(const float* __restrict__ w1,
                            const float* __restrict__ w2,
                            const float* __restrict__ w3,
                            const float* __restrict__ Wmr,
                            const float* __restrict__ Wmc) {
    int i = blockIdx.x * blockDim.x + threadIdx.x;
    if (i < 1800 * 300) {
        int n = i / 300, c = i % 300;
        int g = n / 300, f = n % 300;
        float v;
        if      (g == 0) v = w1[f * 300 + c];
        else if (g == 1) v = w2[(f * 300 + c) * 2 + 0];
        else if (g == 2) v = w2[(f * 300 + c) * 2 + 1];
        else if (g == 3) v = w3[(f * 300 + c) * 3 + 0];
        else if (g == 4) v = w3[(f * 300 + c) * 3 + 1];
        else             v = w3[(f * 300 + c) * 3 + 2];
        g_WcatF[i] = v;
    }
    if (i < ND * NH) {
        int d = i / NH, h = i % NH;
        g_WmrT[i] = Wmr[h * ND + d];
        g_WmcT[i] = Wmc[h * ND + d];
    }
}

// ================= unified WMMA bf16x3 NT GEMM ==============================
// C[M,N] = act(A@B^T + bias); A/B pre-split bf16 hi/lo, rows padded so every
// 128-tile read is in-bounds. staged=0: direct fragment store (C col/row
// padded by caller). staged=1: smem staging + bias/act + bounds guards.
#define LDT 40   // smem tile ld (bf16), 80B rows
#define WSLD 20  // fp32 staging ld — MUST be mult of 4 (wmma 16B ldm rule)
__global__ __launch_bounds__(256) void wgemm_kernel(
    const __nv_bfloat16* __restrict__ Ah, const __nv_bfloat16* __restrict__ Al, int ldA,
    const __nv_bfloat16* __restrict__ Bh, const __nv_bfloat16* __restrict__ Bl, int ldB,
    float* __restrict__ C, int ldc, int nch,
    const float* __restrict__ bias, int act, int M, int N, int staged)
{
    extern __shared__ char sm[];
    uint32_t* sAh = (uint32_t*)sm;                    // [128][20] u32 views
    uint32_t* sAl = sAh + 128 * 20;
    uint32_t* sBh = sAl + 128 * 20;
    uint32_t* sBl = sBh + 128 * 20;
    float* stg = (float*)(sm + 4 * 128 * LDT * 2);    // [8][16*WSLD]
    const int tid = threadIdx.x, wid = tid >> 5, lane = tid & 31;
    const int m0 = blockIdx.y * 128, n0 = blockIdx.x * 128;
    const int wm0 = (wid & 1) * 64, wn0 = (wid >> 1) * 32;
    const int ldau = ldA >> 1, ldbu = ldB >> 1;

    wmma::fragment<wmma::accumulator, 16, 16, 16, float> acc[4][2];
#pragma unroll
    for (int i = 0; i < 4; i++)
#pragma unroll
        for (int j = 0; j < 2; j++) wmma::fill_fragment(acc[i][j], 0.f);

    for (int ch = 0; ch < nch; ch++) {
        const int kb = ch * 32;
        const uint32_t* gAh = (const uint32_t*)Ah + (size_t)m0 * ldau + (kb >> 1);
        const uint32_t* gAl = (const uint32_t*)Al + (size_t)m0 * ldau + (kb >> 1);
        const uint32_t* gBh = (const uint32_t*)Bh + (size_t)n0 * ldbu + (kb >> 1);
        const uint32_t* gBl = (const uint32_t*)Bl + (size_t)n0 * ldbu + (kb >> 1);
#pragma unroll
        for (int u = 0; u < 8; u++) {
            int e = tid + u * 256;
            int r = e >> 4, c = e & 15;
            size_t go = (size_t)r * ldau + c;
            size_t gob = (size_t)r * ldbu + c;
            sAh[r * 20 + c] = gAh[go];
            sAl[r * 20 + c] = gAl[go];
            sBh[r * 20 + c] = gBh[gob];
            sBl[r * 20 + c] = gBl[gob];
        }
        __syncthreads();
#pragma unroll
        for (int ks = 0; ks < 2; ks++) {
            wmma::fragment<wmma::matrix_b, 16, 16, 16, __nv_bfloat16, wmma::col_major> bh[2], bl[2];
#pragma unroll
            for (int j = 0; j < 2; j++) {
                wmma::load_matrix_sync(bh[j], (const __nv_bfloat16*)sBh + (wn0 + j * 16) * LDT + ks * 16, LDT);
                wmma::load_matrix_sync(bl[j], (const __nv_bfloat16*)sBl + (wn0 + j * 16) * LDT + ks * 16, LDT);
            }
#pragma unroll
            for (int i = 0; i < 4; i++) {
                wmma::fragment<wmma::matrix_a, 16, 16, 16, __nv_bfloat16, wmma::row_major> ah, al;
                wmma::load_matrix_sync(ah, (const __nv_bfloat16*)sAh + (wm0 + i * 16) * LDT + ks * 16, LDT);
                wmma::load_matrix_sync(al, (const __nv_bfloat16*)sAl + (wm0 + i * 16) * LDT + ks * 16, LDT);
#pragma unroll
                for (int j = 0; j < 2; j++) {
                    wmma::mma_sync(acc[i][j], ah, bh[j], acc[i][j]);
                    wmma::mma_sync(acc[i][j], ah, bl[j], acc[i][j]);
                    wmma::mma_sync(acc[i][j], al, bh[j], acc[i][j]);
                }
            }
        }
        __syncthreads();
    }

    if (!staged) {
#pragma unroll
        for (int i = 0; i < 4; i++)
#pragma unroll
            for (int j = 0; j < 2; j++)
                wmma::store_matrix_sync(C + (size_t)(m0 + wm0 + i * 16) * ldc + n0 + wn0 + j * 16,
                                        acc[i][j], ldc, wmma::mem_row_major);
    } else {
        float* ws = stg + wid * 16 * WSLD;
#pragma unroll
        for (int i = 0; i < 4; i++)
#pragma unroll
            for (int j = 0; j < 2; j++) {
                wmma::store_matrix_sync(ws, acc[i][j], WSLD, wmma::mem_row_major);
                __syncwarp();
#pragma unroll
                for (int u = 0; u < 8; u++) {
                    int e = lane + u * 32;
                    int rr = e >> 4, cc = e & 15;
                    int gm = m0 + wm0 + i * 16 + rr;
                    int gn = n0 + wn0 + j * 16 + cc;
                    if (gm < M && gn < N) {
                        float v = ws[rr * WSLD + cc];
                        if (bias) v += bias[gn];
                        if (act)  v = sigmoidf_(v);
                        C[(size_t)gm * ldc + gn] = v;
                    }
                }
                __syncwarp();
            }
    }
}

// ================= fused y1 WMMA + epilogue ================================
// block = (128 c-tile, batch b). A = sigmoid(cand*fu) built & split on the fly.
#define CLD 132  // fp32 C-tile ld (multiple of 4 for wmma store)
__global__ __launch_bounds__(256) void final_wmma_kernel(
    const float* __restrict__ Wj, const float* __restrict__ bd,
    const float* __restrict__ bj,
    const float* __restrict__ ypast, float* __restrict__ out)
{
    extern __shared__ char sm[];
    uint32_t* sAh = (uint32_t*)sm;
    uint32_t* sAl = sAh + 128 * 20;
    uint32_t* sBh = sAl + 128 * 20;
    uint32_t* sBl = sBh + 128 * 20;
    __shared__ float fu_s[ND];
    __shared__ float Wj_s[NH], bd_s[NH];
    const int tid = threadIdx.x, wid = tid >> 5;
    const int c0 = blockIdx.x * 128, b = blockIdx.y;
    const int wm0 = (wid & 1) * 64, wn0 = (wid >> 1) * 32;

    for (int i = tid; i < ND; i += 256) fu_s[i] = g_fu[b * ND + i];
    if (tid < NH) { Wj_s[tid] = Wj[tid]; bd_s[tid] = bd[tid]; }
    __syncthreads();

    wmma::fragment<wmma::accumulator, 16, 16, 16, float> acc[4][2];
#pragma unroll
    for (int i = 0; i < 4; i++)
#pragma unroll
        for (int j = 0; j < 2; j++) wmma::fill_fragment(acc[i][j], 0.f);

    const uint32_t* gWdh = (const uint32_t*)g_Wd_h;
    const uint32_t* gWdl = (const uint32_t*)g_Wd_l;

    for (int ch = 0; ch < 10; ch++) {
        const int kb = ch * 32;
#pragma unroll
        for (int u = 0; u < 8; u++) {       // A: sigmoid(cand*fu), split
            int e = tid + u * 256;
            int r = e >> 4, pc = e & 15;
            int k = kb + pc * 2, gc = c0 + r;
            float a0 = 0.f, a1 = 0.f;
            if (gc < NC) {
                if (k < ND)     a0 = sigmoidf_(g_cand[(size_t)gc * ND + k] * fu_s[k]);
                if (k + 1 < ND) a1 = sigmoidf_(g_cand[(size_t)gc * ND + k + 1] * fu_s[k + 1]);
            }
            __nv_bfloat16 h0, l0, h1, l1;
            split_bf(a0, h0, l0); split_bf(a1, h1, l1);
            sAh[r * 20 + pc] = pack_bf(h0, h1);
            sAl[r * 20 + pc] = pack_bf(l0, l1);
            // B: copy pre-split Wd
            size_t go = (size_t)r * (KP300 >> 1) + (kb >> 1) + pc;
            sBh[r * 20 + pc] = gWdh[go];
            sBl[r * 20 + pc] = gWdl[go];
        }
        __syncthreads();
#pragma unroll
        for (int ks = 0; ks < 2; ks++) {
            wmma::fragment<wmma::matrix_b, 16, 16, 16, __nv_bfloat16, wmma::col_major> bh[2], bl[2];
#pragma unroll
            for (int j = 0; j < 2; j++) {
                wmma::load_matrix_sync(bh[j], (const __nv_bfloat16*)sBh + (wn0 + j * 16) * LDT + ks * 16, LDT);
                wmma::load_matrix_sync(bl[j], (const __nv_bfloat16*)sBl + (wn0 + j * 16) * LDT + ks * 16, LDT);
            }
#pragma unroll
            for (int i = 0; i < 4; i++) {
                wmma::fragment<wmma::matrix_a, 16, 16, 16, __nv_bfloat16, wmma::row_major> ah, al;
                wmma::load_matrix_sync(ah, (const __nv_bfloat16*)sAh + (wm0 + i * 16) * LDT + ks * 16, LDT);
                wmma::load_matrix_sync(al, (const __nv_bfloat16*)sAl + (wm0 + i * 16) * LDT + ks * 16, LDT);
#pragma unroll
                for (int j = 0; j < 2; j++) {
                    wmma::mma_sync(acc[i][j], ah, bh[j], acc[i][j]);
                    wmma::mma_sync(acc[i][j], ah, bl[j], acc[i][j]);
                    wmma::mma_sync(acc[i][j], al, bh[j], acc[i][j]);
                }
            }
        }
        __syncthreads();
    }

    // epilogue: stage C tile to smem (tiles dead), reduce with Wj
    float* Ct = (float*)sm;   // [128][CLD]
#pragma unroll
    for (int i = 0; i < 4; i++)
#pragma unroll
        for (int j = 0; j < 2; j++)
            wmma::store_matrix_sync(Ct + (wm0 + i * 16) * CLD + wn0 + j * 16,
                                    acc[i][j], CLD, wmma::mem_row_major);
    __syncthreads();
    if (tid < 128) {
        int gc = c0 + tid;
        const float* row = Ct + tid * CLD;
        float y = 0.f;
#pragma unroll 4
        for (int h = 0; h < NH; h++)
            y += Wj_s[h] * sigmoidf_(bd_s[h] + row[h]);
        if (gc < NC) {
            float tot = bj[0] + y + g_y23[gc];
            out[(size_t)b * NC + gc] = 0.5f * tot + 0.5f * ypast[(size_t)b * NC + gc];
        }
    }
}

// ---------------- conv combine: shift-add, relu, maxpool --------------------
__global__ void pool_kernel(const float* __restrict__ b1,
                            const float* __restrict__ b2,
                            const float* __restrict__ b3) {
    int b = blockIdx.x;
    int f = threadIdx.x;
    if (f >= ND) return;
    const float* Gb = g_G + (size_t)b * NL * GLD;
    float m1 = -1e30f, m2 = -1e30f, m3 = -1e30f;
    for (int t = 0; t < NL; t++)
        m1 = fmaxf(m1, Gb[t * GLD + f]);
    for (int t = 0; t < NL - 1; t++)
        m2 = fmaxf(m2, Gb[t * GLD + 300 + f] + Gb[(t + 1) * GLD + 600 + f]);
    for (int t = 0; t < NL - 2; t++)
        m3 = fmaxf(m3, Gb[t * GLD + 900 + f] + Gb[(t + 1) * GLD + 1200 + f]
                       + Gb[(t + 2) * GLD + 1500 + f]);
    g_fu[b * ND + f] = fmaxf(m1 + b1[f], 0.f) + fmaxf(m2 + b2[f], 0.f)
                     + fmaxf(m3 + b3[f], 0.f);
}

// ---------------- fused gates: m_r, m_c, y2+y3 ------------------------------
__global__ void gates_kernel(const float* __restrict__ bmr,
                             const float* __restrict__ bmc,
                             const float* __restrict__ Wj,
                             const float* __restrict__ bj) {
    const int c0 = blockIdx.x * 4;
    __shared__ __align__(16) float Pr[NB][4];
    __shared__ __align__(16) float Qr[NB][4];
    __shared__ __align__(16) float sA[2][ND][4];
    __shared__ float red[200][4];
    const int t = threadIdx.x;  // 384

    for (int e = t; e < 4 * NB; e += 384) {
        int bb = e >> 2, ci = e & 3;
        const float* row = g_PTT + (size_t)(c0 + ci) * 384;
        Pr[bb][ci] = row[bb];
        Qr[bb][ci] = row[128 + bb] * row[256 + bb];
    }
    __syncthreads();

    if (t < ND) {
        float ar[4] = {0.f, 0.f, 0.f, 0.f};
        float ac[4] = {0.f, 0.f, 0.f, 0.f};
        for (int b = 0; b < NB; b++) {
            float f = g_fu[b * ND + t];
            float4 p = *(const float4*)&Pr[b][0];
            float4 q = *(const float4*)&Qr[b][0];
            ar[0] += p.x * f; ar[1] += p.y * f; ar[2] += p.z * f; ar[3] += p.w * f;
            ac[0] += q.x * f; ac[1] += q.y * f; ac[2] += q.z * f; ac[3] += q.w * f;
        }
#pragma unroll
        for (int ci = 0; ci < 4; ci++) {
            sA[0][t][ci] = sigmoidf_(ar[ci]);
            sA[1][t][ci] = sigmoidf_(ac[ci]);
        }
    }
    __syncthreads();

    if (t < 2 * NH) {
        int which = t / NH, h = t % NH;
        const float* WmT = which ? g_WmcT : g_WmrT;
        float bb = which ? bmc[h] : bmr[h];
        float a[4] = {bb, bb, bb, bb};
        for (int d = 0; d < ND; d++) {
            float w = WmT[d * NH + h];
            float4 s = *(const float4*)&sA[which][d][0];
            a[0] += w * s.x; a[1] += w * s.y; a[2] += w * s.z; a[3] += w * s.w;
        }
        float wj = Wj[h];
#pragma unroll
        for (int ci = 0; ci < 4; ci++) red[t][ci] = wj * sigmoidf_(a[ci]);
    }
    __syncthreads();

    if (t < 4) {
        float s = 0.f;
        for (int e = 0; e < 2 * NH; e++) s += red[e][t];
        g_y23[c0 + t] = s + 2.f * bj[0];
    }
}

// ---------------- launch -----------------------------------------------------
extern "C" void kernel_launch(void* const* d_in, const int* in_sizes, int n_in,
                              void* d_out, int out_size) {
    const float* utt      = (const float*)d_in[0];
    const float* sys_s    = (const float*)d_in[1];
    const float* conf_s   = (const float*)d_in[2];
    const float* conf_v   = (const float*)d_in[3];
    const float* ypast    = (const float*)d_in[4];
    const float* slot_emb = (const float*)d_in[5];
    const float* val_emb  = (const float*)d_in[6];
    const float* Wc       = (const float*)d_in[7];
    const float* bc       = (const float*)d_in[8];
    const float* cw1      = (const float*)d_in[9];
    const float* cb1      = (const float*)d_in[10];
    const float* cw2      = (const float*)d_in[11];
    const float* cb2      = (const float*)d_in[12];
    const float* cw3      = (const float*)d_in[13];
    const float* cb3      = (const float*)d_in[14];
    const float* Wd       = (const float*)d_in[15];
    const float* bd       = (const float*)d_in[16];
    const float* Wmr      = (const float*)d_in[17];
    const float* bmr      = (const float*)d_in[18];
    const float* Wmc      = (const float*)d_in[19];
    const float* bmc      = (const float*)d_in[20];
    const float* Wj       = (const float*)d_in[21];
    const float* bj       = (const float*)d_in[22];
    float* out = (float*)d_out;
    (void)in_sizes; (void)n_in; (void)out_size;

    // REAL device addresses (host-shadow/ATS trap).
    float *p_WcatF, *p_G, *p_cand, *p_PTT;
    __nv_bfloat16 *p_utt_h, *p_utt_l, *p_Wcat_h, *p_Wcat_l;
    __nv_bfloat16 *p_catSV_h, *p_catSV_l, *p_Wc_h, *p_Wc_l;
    __nv_bfloat16 *p_slot_h, *p_slot_l, *p_val_h, *p_val_l;
    __nv_bfloat16 *p_B3_h, *p_B3_l, *p_Wd_h, *p_Wd_l;
    cudaGetSymbolAddress((void**)&p_WcatF,   g_WcatF);
    cudaGetSymbolAddress((void**)&p_G,       g_G);
    cudaGetSymbolAddress((void**)&p_cand,    g_cand);
    cudaGetSymbolAddress((void**)&p_PTT,     g_PTT);
    cudaGetSymbolAddress((void**)&p_utt_h,   g_utt_h);
    cudaGetSymbolAddress((void**)&p_utt_l,   g_utt_l);
    cudaGetSymbolAddress((void**)&p_Wcat_h,  g_Wcat_h);
    cudaGetSymbolAddress((void**)&p_Wcat_l,  g_Wcat_l);
    cudaGetSymbolAddress((void**)&p_catSV_h, g_catSV_h);
    cudaGetSymbolAddress((void**)&p_catSV_l, g_catSV_l);
    cudaGetSymbolAddress((void**)&p_Wc_h,    g_Wc_h);
    cudaGetSymbolAddress((void**)&p_Wc_l,    g_Wc_l);
    cudaGetSymbolAddress((void**)&p_slot_h,  g_slot_h);
    cudaGetSymbolAddress((void**)&p_slot_l,  g_slot_l);
    cudaGetSymbolAddress((void**)&p_val_h,   g_val_h);
    cudaGetSymbolAddress((void**)&p_val_l,   g_val_l);
    cudaGetSymbolAddress((void**)&p_B3_h,    g_B3_h);
    cudaGetSymbolAddress((void**)&p_B3_l,    g_B3_l);
    cudaGetSymbolAddress((void**)&p_Wd_h,    g_Wd_h);
    cudaGetSymbolAddress((void**)&p_Wd_l,    g_Wd_l);

    const int GEMM_SMEM  = 4 * 128 * LDT * 2 + 8 * 16 * WSLD * 4;  // 40960+10240=51200
    const int FINAL_SMEM = 128 * CLD * 4;                          // 67584
    cudaFuncSetAttribute(wgemm_kernel,
                         cudaFuncAttributeMaxDynamicSharedMemorySize, GEMM_SMEM);
    cudaFuncSetAttribute(final_wmma_kernel,
                         cudaFuncAttributeMaxDynamicSharedMemorySize, FINAL_SMEM);

    auto split = [&](const float* src, int M, int K, __nv_bfloat16* dh,
                     __nv_bfloat16* dl, int Kpad, int ro, int co) {
        presplit_kernel<<<(M * K + 255) / 256, 256>>>(src, M, K, dh, dl, Kpad, ro, co);
    };

    // 1. pack Wcat fp32 + WmT
    pack_kernel<<<(540000 + 255) / 256, 256>>>(cw1, cw2, cw3, Wmr, Wmc);

    // 2. presplit all static GEMM operands
    split(utt,      5120, 300, p_utt_h,   p_utt_l,   KP300, 0, 0);
    split(p_WcatF,  1800, 300, p_Wcat_h,  p_Wcat_l,  KP300, 0, 0);
    split(slot_emb, 1000, 300, p_slot_h,  p_slot_l,  KP300, 0, 0);
    split(val_emb,  1000, 300, p_val_h,   p_val_l,   KP300, 0, 0);
    split(slot_emb, 1000, 300, p_catSV_h, p_catSV_l, KP600, 0, 0);
    split(val_emb,  1000, 300, p_catSV_h, p_catSV_l, KP600, 0, 300);
    split(Wc,       300,  600, p_Wc_h,    p_Wc_l,    KP600, 0, 0);
    split(sys_s,    128,  300, p_B3_h,    p_B3_l,    KP300, 0,   0);
    split(conf_s,   128,  300, p_B3_h,    p_B3_l,    KP300, 128, 0);
    split(conf_v,   128,  300, p_B3_h,    p_B3_l,    KP300, 256, 0);
    split(Wd,       100,  300, p_Wd_h,    p_Wd_l,    KP300, 0, 0);

    // 3. conv GEMM: G[5120,1800(pad 1920)] = utt @ Wcat^T (direct store)
    wgemm_kernel<<<dim3(15, 40), 256, GEMM_SMEM>>>(
        p_utt_h, p_utt_l, KP300, p_Wcat_h, p_Wcat_l, KP300,
        p_G, GLD, 10, nullptr, 0, 5120, 1800, 0);

    // 4. pool -> fu
    pool_kernel<<<NB, 320>>>(cb1, cb2, cb3);

    // 5. cand = sigmoid(catSV @ Wc^T + bc) (staged epilogue)
    wgemm_kernel<<<dim3(3, 8), 256, GEMM_SMEM>>>(
        p_catSV_h, p_catSV_l, KP600, p_Wc_h, p_Wc_l, KP600,
        p_cand, 300, 19, bc, 1, NC, ND, 1);

    // 6. PTT: [P|T1] = slot @ [sys;conf_s]^T ; [T2] = val @ conf_v^T
    wgemm_kernel<<<dim3(2, 8), 256, GEMM_SMEM>>>(
        p_slot_h, p_slot_l, KP300, p_B3_h, p_B3_l, KP300,
        p_PTT, 384, 10, nullptr, 0, NC, 256, 0);
    wgemm_kernel<<<dim3(1, 8), 256, GEMM_SMEM>>>(
        p_val_h, p_val_l, KP300, p_B3_h + (size_t)256 * KP300, p_B3_l + (size_t)256 * KP300, KP300,
        p_PTT + 256, 384, 10, nullptr, 0, NC, 128, 0);

    // 7. gates (m_r, m_c, y2+y3; Q = T1*T2 inline)
    gates_kernel<<<NC / 4, 384>>>(bmr, bmc, Wj, bj);

    // 8. fused y1 + combine + output
    final_wmma_kernel<<<dim3(8, NB), 256, FINAL_SMEM>>>(Wj, bd, bj, ypast, out);
}

// round 16
// speedup vs baseline: 1.9166x; 1.0954x over previous
#include <cuda_runtime.h>
#include <cuda_bf16.h>
#include <cuda_pipeline.h>
#include <mma.h>
#include <math.h>
#include <stdint.h>

using namespace nvcuda;

#define NB 128
#define NC 1000
#define ND 300
#define NL 40
#define NH 100

#define KP300 320     // K=300 padded to 10 chunks of 32
#define KP600 608     // K=600 padded to 19 chunks of 32
#define GLD   1920    // g_G column pad (15 n-tiles of 128)

// ---------------- scratch (device globals; zero-initialized, no alloc) -----
__device__ __align__(16) float g_WcatF[1800 * 300];
__device__ __align__(16) __nv_bfloat16 g_utt_h[5120 * KP300],  g_utt_l[5120 * KP300];
__device__ __align__(16) __nv_bfloat16 g_Wcat_h[1920 * KP300], g_Wcat_l[1920 * KP300];
__device__ __align__(16) __nv_bfloat16 g_catSV_h[1024 * KP600], g_catSV_l[1024 * KP600];
__device__ __align__(16) __nv_bfloat16 g_Wc_h[384 * KP600],    g_Wc_l[384 * KP600];
__device__ __align__(16) __nv_bfloat16 g_slot_h[1024 * KP300], g_slot_l[1024 * KP300];
__device__ __align__(16) __nv_bfloat16 g_val_h[1024 * KP300],  g_val_l[1024 * KP300];
__device__ __align__(16) __nv_bfloat16 g_B3_h[384 * KP300],    g_B3_l[384 * KP300];
__device__ __align__(16) __nv_bfloat16 g_Wd_h[128 * KP300],    g_Wd_l[128 * KP300];
__device__ __align__(16) float g_G[5120 * GLD];     // conv pre-act, col-padded
__device__ __align__(16) float g_fu[NB * ND];
__device__ __align__(16) float g_cand[NC * ND];
__device__ __align__(16) float g_PTT[1024 * 384];   // [P | T1 | T2]
__device__ __align__(16) float g_WmrT[ND * NH];
__device__ __align__(16) float g_WmcT[ND * NH];
__device__ float g_y23[NC];

__device__ __forceinline__ float sigmoidf_(float x) {
    return 1.0f / (1.0f + __expf(-x));
}

__device__ __forceinline__ void split_bf(float x, __nv_bfloat16& h, __nv_bfloat16& l) {
    h = __float2bfloat16_rn(x);
    l = __float2bfloat16_rn(x - __bfloat162float(h));
}

__device__ __forceinline__ uint32_t pack_bf(__nv_bfloat16 a, __nv_bfloat16 b) {
    return (uint32_t)__bfloat16_as_ushort(a) | ((uint32_t)__bfloat16_as_ushort(b) << 16);
}

__device__ __forceinline__ void st_split(float x, __nv_bfloat16* dh,
                                         __nv_bfloat16* dl, size_t o) {
    __nv_bfloat16 h, l;
    split_bf(x, h, l);
    dh[o] = h; dl[o] = l;
}

// ---------------- presplit A: utt only --------------------------------------
__global__ void presplitA_kernel(const float* __restrict__ utt) {
    int i = blockIdx.x * blockDim.x + threadIdx.x;
    if (i >= 5120 * 300) return;
    int r = i / 300, c = i % 300;
    st_split(utt[i], g_utt_h, g_utt_l, (size_t)r * KP300 + c);
}

// ---------------- presplit B: all static operands (segment chain) -----------
__global__ void presplitB_kernel(const float* __restrict__ slot,
                                 const float* __restrict__ val,
                                 const float* __restrict__ Wc,
                                 const float* __restrict__ sys_s,
                                 const float* __restrict__ conf_s,
                                 const float* __restrict__ conf_v,
                                 const float* __restrict__ Wd) {
    int i = blockIdx.x * blockDim.x + threadIdx.x;
    // 1: WcatF [1800,300] -> Wcat
    if (i < 540000) {
        int r = i / 300, c = i % 300;
        st_split(g_WcatF[i], g_Wcat_h, g_Wcat_l, (size_t)r * KP300 + c);
        return;
    }
    i -= 540000;
    // 2: slot -> slot_h
    if (i < 300000) {
        int r = i / 300, c = i % 300;
        st_split(slot[i], g_slot_h, g_slot_l, (size_t)r * KP300 + c);
        return;
    }
    i -= 300000;
    // 3: val -> val_h
    if (i < 300000) {
        int r = i / 300, c = i % 300;
        st_split(val[i], g_val_h, g_val_l, (size_t)r * KP300 + c);
        return;
    }
    i -= 300000;
    // 4: slot -> catSV cols [0,300)
    if (i < 300000) {
        int r = i / 300, c = i % 300;
        st_split(slot[i], g_catSV_h, g_catSV_l, (size_t)r * KP600 + c);
        return;
    }
    i -= 300000;
    // 5: val -> catSV cols [300,600)
    if (i < 300000) {
        int r = i / 300, c = i % 300;
        st_split(val[i], g_catSV_h, g_catSV_l, (size_t)r * KP600 + 300 + c);
        return;
    }
    i -= 300000;
    // 6: Wc [300,600]
    if (i < 180000) {
        int r = i / 600, c = i % 600;
        st_split(Wc[i], g_Wc_h, g_Wc_l, (size_t)r * KP600 + c);
        return;
    }
    i -= 180000;
    // 7-9: sys / conf_s / conf_v -> B3 rows 0/128/256
    if (i < 115200) {
        int seg = i / 38400, j = i % 38400;
        int r = j / 300, c = j % 300;
        const float* src = (seg == 0) ? sys_s : (seg == 1) ? conf_s : conf_v;
        st_split(src[j], g_B3_h, g_B3_l, (size_t)(seg * 128 + r) * KP300 + c);
        return;
    }
    i -= 115200;
    // 10: Wd [100,300]
    if (i < 30000) {
        int r = i / 300, c = i % 300;
        st_split(Wd[i], g_Wd_h, g_Wd_l, (size_t)r * KP300 + c);
    }
}
#define PREB_TOTAL (540000 + 4 * 300000 + 180000 + 115200 + 30000)

// ---------------- pack: Wcat fp32 + WmT transposes --------------------------
__global__ void pack_kernel(const float* __restrict__ w1,
                            const float* __restrict__ w2,
                            const float* __restrict__ w3,
                            const float* __restrict__ Wmr,
                            const float* __restrict__ Wmc) {
    int i = blockIdx.x * blockDim.x + threadIdx.x;
    if (i < 1800 * 300) {
        int n = i / 300, c = i % 300;
        int g = n / 300, f = n % 300;
        float v;
        if      (g == 0) v = w1[f * 300 + c];
        else if (g == 1) v = w2[(f * 300 + c) * 2 + 0];
        else if (g == 2) v = w2[(f * 300 + c) * 2 + 1];
        else if (g == 3) v = w3[(f * 300 + c) * 3 + 0];
        else if (g == 4) v = w3[(f * 300 + c) * 3 + 1];
        else             v = w3[(f * 300 + c) * 3 + 2];
        g_WcatF[i] = v;
    }
    if (i < ND * NH) {
        int d = i / NH, h = i % NH;
        g_WmrT[i] = Wmr[h * ND + d];
        g_WmcT[i] = Wmc[h * ND + d];
    }
}

// ================= WMMA bf16x3 NT GEMM body (cp.async double-buffered) ======
#define LDT 40   // smem tile ld (bf16), 80B rows (conflict-free for ldmatrix)
#define WSLD 20  // fp32 staging ld — mult of 4 (wmma 16B ldm rule)
#define BUFU (4 * 128 * 20)   // u32 per buffer (4 arrays of 128x20)

// async-fill one buffer with chunk kc (u32 col offset = ch*16)
__device__ __forceinline__ void wfill(uint32_t* d,
                                      const uint32_t* gAh, const uint32_t* gAl, int ldau,
                                      const uint32_t* gBh, const uint32_t* gBl, int ldbu,
                                      int kc, int tid) {
#pragma unroll
    for (int u = 0; u < 4; u++) {
        int e = tid + u * 256;
        int r = e >> 3, p = (e & 7) * 2;
        size_t ga = (size_t)r * ldau + kc + p;
        size_t gb = (size_t)r * ldbu + kc + p;
        __pipeline_memcpy_async(d + 0 * 2560 + r * 20 + p, gAh + ga, 8);
        __pipeline_memcpy_async(d + 1 * 2560 + r * 20 + p, gAl + ga, 8);
        __pipeline_memcpy_async(d + 2 * 2560 + r * 20 + p, gBh + gb, 8);
        __pipeline_memcpy_async(d + 3 * 2560 + r * 20 + p, gBl + gb, 8);
    }
}

__device__ __forceinline__ void wgemm_body(
    const __nv_bfloat16* Ah, const __nv_bfloat16* Al, int ldA,
    const __nv_bfloat16* Bh, const __nv_bfloat16* Bl, int ldB,
    float* C, int ldc, int nch,
    const float* bias, int act, int M, int N, int staged,
    int m0, int n0, char* sm)
{
    uint32_t* b0 = (uint32_t*)sm;
    float* stg = (float*)(sm + 2 * BUFU * 4);
    const int tid = threadIdx.x, wid = tid >> 5, lane = tid & 31;
    const int wm0 = (wid & 1) * 64, wn0 = (wid >> 1) * 32;
    const int ldau = ldA >> 1, ldbu = ldB >> 1;
    const uint32_t* gAh = (const uint32_t*)Ah + (size_t)m0 * ldau;
    const uint32_t* gAl = (const uint32_t*)Al + (size_t)m0 * ldau;
    const uint32_t* gBh = (const uint32_t*)Bh + (size_t)n0 * ldbu;
    const uint32_t* gBl = (const uint32_t*)Bl + (size_t)n0 * ldbu;

    wmma::fragment<wmma::accumulator, 16, 16, 16, float> acc[4][2];
#pragma unroll
    for (int i = 0; i < 4; i++)
#pragma unroll
        for (int j = 0; j < 2; j++) wmma::fill_fragment(acc[i][j], 0.f);

    wfill(b0, gAh, gAl, ldau, gBh, gBl, ldbu, 0, tid);
    __pipeline_commit();
    int cur = 0;

    for (int ch = 0; ch < nch; ch++) {
        __pipeline_wait_prior(0);
        __syncthreads();                 // chunk ch visible; all warps past mma(ch-1)
        if (ch + 1 < nch) {
            wfill(b0 + (cur ^ 1) * BUFU, gAh, gAl, ldau, gBh, gBl, ldbu,
                  (ch + 1) * 16, tid);
            __pipeline_commit();
        }
        const __nv_bfloat16* sAh = (const __nv_bfloat16*)(b0 + cur * BUFU);
        const __nv_bfloat16* sAl = sAh + 5120;
        const __nv_bfloat16* sBh = sAh + 10240;
        const __nv_bfloat16* sBl = sAh + 15360;
#pragma unroll
        for (int ks = 0; ks < 2; ks++) {
            wmma::fragment<wmma::matrix_b, 16, 16, 16, __nv_bfloat16, wmma::col_major> bh[2], bl[2];
#pragma unroll
            for (int j = 0; j < 2; j++) {
                wmma::load_matrix_sync(bh[j], sBh + (wn0 + j * 16) * LDT + ks * 16, LDT);
                wmma::load_matrix_sync(bl[j], sBl + (wn0 + j * 16) * LDT + ks * 16, LDT);
            }
#pragma unroll
            for (int i = 0; i < 4; i++) {
                wmma::fragment<wmma::matrix_a, 16, 16, 16, __nv_bfloat16, wmma::row_major> ah, al;
                wmma::load_matrix_sync(ah, sAh + (wm0 + i * 16) * LDT + ks * 16, LDT);
                wmma::load_matrix_sync(al, sAl + (wm0 + i * 16) * LDT + ks * 16, LDT);
#pragma unroll
                for (int j = 0; j < 2; j++) {
                    wmma::mma_sync(acc[i][j], ah, bh[j], acc[i][j]);
                    wmma::mma_sync(acc[i][j], ah, bl[j], acc[i][j]);
                    wmma::mma_sync(acc[i][j], al, bh[j], acc[i][j]);
                }
            }
        }
        cur ^= 1;
    }

    if (!staged) {
#pragma unroll
        for (int i = 0; i < 4; i++)
#pragma unroll
            for (int j = 0; j < 2; j++)
                wmma::store_matrix_sync(C + (size_t)(m0 + wm0 + i * 16) * ldc + n0 + wn0 + j * 16,
                                        acc[i][j], ldc, wmma::mem_row_major);
    } else {
        float* ws = stg + wid * 16 * WSLD;
#pragma unroll
        for (int i = 0; i < 4; i++)
#pragma unroll
            for (int j = 0; j < 2; j++) {
                wmma::store_matrix_sync(ws, acc[i][j], WSLD, wmma::mem_row_major);
                __syncwarp();
#pragma unroll
                for (int u = 0; u < 8; u++) {
                    int e = lane + u * 32;
                    int rr = e >> 4, cc = e & 15;
                    int gm = m0 + wm0 + i * 16 + rr;
                    int gn = n0 + wn0 + j * 16 + cc;
                    if (gm < M && gn < N) {
                        float v = ws[rr * WSLD + cc];
                        if (bias) v += bias[gn];
                        if (act)  v = sigmoidf_(v);
                        C[(size_t)gm * ldc + gn] = v;
                    }
                }
                __syncwarp();
            }
    }
}

__global__ __launch_bounds__(256) void wgemm_kernel(
    const __nv_bfloat16* __restrict__ Ah, const __nv_bfloat16* __restrict__ Al, int ldA,
    const __nv_bfloat16* __restrict__ Bh, const __nv_bfloat16* __restrict__ Bl, int ldB,
    float* __restrict__ C, int ldc, int nch,
    const float* __restrict__ bias, int act, int M, int N, int staged)
{
    extern __shared__ char sm[];
    wgemm_body(Ah, Al, ldA, Bh, Bl, ldB, C, ldc, nch, bias, act, M, N, staged,
               blockIdx.y * 128, blockIdx.x * 128, sm);
}

// PTT in ONE launch: bx<2 -> P|T1 = slot @ B3[0:256]^T ; bx==2 -> T2 = val @ B3[256:384]^T
__global__ __launch_bounds__(256) void ptt_kernel() {
    extern __shared__ char sm[];
    if (blockIdx.x < 2) {
        wgemm_body(g_slot_h, g_slot_l, KP300, g_B3_h, g_B3_l, KP300,
                   g_PTT, 384, 10, nullptr, 0, 0, 0, 0,
                   blockIdx.y * 128, blockIdx.x * 128, sm);
    } else {
        wgemm_body(g_val_h, g_val_l, KP300,
                   g_B3_h + (size_t)256 * KP300, g_B3_l + (size_t)256 * KP300, KP300,
                   g_PTT + 256, 384, 10, nullptr, 0, 0, 0, 0,
                   blockIdx.y * 128, 0, sm);
    }
}

// ================= fused y1 WMMA + epilogue (unchanged) =====================
#define CLD 132
__global__ __launch_bounds__(256) void final_wmma_kernel(
    const float* __restrict__ Wj, const float* __restrict__ bd,
    const float* __restrict__ bj,
    const float* __restrict__ ypast, float* __restrict__ out)
{
    extern __shared__ char sm[];
    uint32_t* sAh = (uint32_t*)sm;
    uint32_t* sAl = sAh + 128 * 20;
    uint32_t* sBh = sAl + 128 * 20;
    uint32_t* sBl = sBh + 128 * 20;
    __shared__ float fu_s[ND];
    __shared__ float Wj_s[NH], bd_s[NH];
    const int tid = threadIdx.x, wid = tid >> 5;
    const int c0 = blockIdx.x * 128, b = blockIdx.y;
    const int wm0 = (wid & 1) * 64, wn0 = (wid >> 1) * 32;

    for (int i = tid; i < ND; i += 256) fu_s[i] = g_fu[b * ND + i];
    if (tid < NH) { Wj_s[tid] = Wj[tid]; bd_s[tid] = bd[tid]; }
    __syncthreads();

    wmma::fragment<wmma::accumulator, 16, 16, 16, float> acc[4][2];
#pragma unroll
    for (int i = 0; i < 4; i++)
#pragma unroll
        for (int j = 0; j < 2; j++) wmma::fill_fragment(acc[i][j], 0.f);

    const uint32_t* gWdh = (const uint32_t*)g_Wd_h;
    const uint32_t* gWdl = (const uint32_t*)g_Wd_l;

    for (int ch = 0; ch < 10; ch++) {
        const int kb = ch * 32;
#pragma unroll
        for (int u = 0; u < 8; u++) {
            int e = tid + u * 256;
            int r = e >> 4, pc = e & 15;
            int k = kb + pc * 2, gc = c0 + r;
            float a0 = 0.f, a1 = 0.f;
            if (gc < NC) {
                if (k < ND)     a0 = sigmoidf_(g_cand[(size_t)gc * ND + k] * fu_s[k]);
                if (k + 1 < ND) a1 = sigmoidf_(g_cand[(size_t)gc * ND + k + 1] * fu_s[k + 1]);
            }
            __nv_bfloat16 h0, l0, h1, l1;
            split_bf(a0, h0, l0); split_bf(a1, h1, l1);
            sAh[r * 20 + pc] = pack_bf(h0, h1);
            sAl[r * 20 + pc] = pack_bf(l0, l1);
            size_t go = (size_t)r * (KP300 >> 1) + (kb >> 1) + pc;
            sBh[r * 20 + pc] = gWdh[go];
            sBl[r * 20 + pc] = gWdl[go];
        }
        __syncthreads();
#pragma unroll
        for (int ks = 0; ks < 2; ks++) {
            wmma::fragment<wmma::matrix_b, 16, 16, 16, __nv_bfloat16, wmma::col_major> bh[2], bl[2];
#pragma unroll
            for (int j = 0; j < 2; j++) {
                wmma::load_matrix_sync(bh[j], (const __nv_bfloat16*)sBh + (wn0 + j * 16) * LDT + ks * 16, LDT);
                wmma::load_matrix_sync(bl[j], (const __nv_bfloat16*)sBl + (wn0 + j * 16) * LDT + ks * 16, LDT);
            }
#pragma unroll
            for (int i = 0; i < 4; i++) {
                wmma::fragment<wmma::matrix_a, 16, 16, 16, __nv_bfloat16, wmma::row_major> ah, al;
                wmma::load_matrix_sync(ah, (const __nv_bfloat16*)sAh + (wm0 + i * 16) * LDT + ks * 16, LDT);
                wmma::load_matrix_sync(al, (const __nv_bfloat16*)sAl + (wm0 + i * 16) * LDT + ks * 16, LDT);
#pragma unroll
                for (int j = 0; j < 2; j++) {
                    wmma::mma_sync(acc[i][j], ah, bh[j], acc[i][j]);
                    wmma::mma_sync(acc[i][j], ah, bl[j], acc[i][j]);
                    wmma::mma_sync(acc[i][j], al, bh[j], acc[i][j]);
                }
            }
        }
        __syncthreads();
    }

    float* Ct = (float*)sm;   // [128][CLD]
#pragma unroll
    for (int i = 0; i < 4; i++)
#pragma unroll
        for (int j = 0; j < 2; j++)
            wmma::store_matrix_sync(Ct + (wm0 + i * 16) * CLD + wn0 + j * 16,
                                    acc[i][j], CLD, wmma::mem_row_major);
    __syncthreads();
    if (tid < 128) {
        int gc = c0 + tid;
        const float* row = Ct + tid * CLD;
        float y = 0.f;
#pragma unroll 4
        for (int h = 0; h < NH; h++)
            y += Wj_s[h] * sigmoidf_(bd_s[h] + row[h]);
        if (gc < NC) {
            float tot = bj[0] + y + g_y23[gc];
            out[(size_t)b * NC + gc] = 0.5f * tot + 0.5f * ypast[(size_t)b * NC + gc];
        }
    }
}

// ---------------- conv combine: shift-add, relu, maxpool --------------------
__global__ void pool_kernel(const float* __restrict__ b1,
                            const float* __restrict__ b2,
                            const float* __restrict__ b3) {
    int b = blockIdx.x;
    int f = threadIdx.x;
    if (f >= ND) return;
    const float* Gb = g_G + (size_t)b * NL * GLD;
    float m1 = -1e30f, m2 = -1e30f, m3 = -1e30f;
    for (int t = 0; t < NL; t++)
        m1 = fmaxf(m1, Gb[t * GLD + f]);
    for (int t = 0; t < NL - 1; t++)
        m2 = fmaxf(m2, Gb[t * GLD + 300 + f] + Gb[(t + 1) * GLD + 600 + f]);
    for (int t = 0; t < NL - 2; t++)
        m3 = fmaxf(m3, Gb[t * GLD + 900 + f] + Gb[(t + 1) * GLD + 1200 + f]
                       + Gb[(t + 2) * GLD + 1500 + f]);
    g_fu[b * ND + f] = fmaxf(m1 + b1[f], 0.f) + fmaxf(m2 + b2[f], 0.f)
                     + fmaxf(m3 + b3[f], 0.f);
}

// ---------------- fused gates: m_r, m_c, y2+y3 ------------------------------
__global__ void gates_kernel(const float* __restrict__ bmr,
                             const float* __restrict__ bmc,
                             const float* __restrict__ Wj,
                             const float* __restrict__ bj) {
    const int c0 = blockIdx.x * 4;
    __shared__ __align__(16) float Pr[NB][4];
    __shared__ __align__(16) float Qr[NB][4];
    __shared__ __align__(16) float sA[2][ND][4];
    __shared__ float red[200][4];
    const int t = threadIdx.x;  // 384

    for (int e = t; e < 4 * NB; e += 384) {
        int bb = e >> 2, ci = e & 3;
        const float* row = g_PTT + (size_t)(c0 + ci) * 384;
        Pr[bb][ci] = row[bb];
        Qr[bb][ci] = row[128 + bb] * row[256 + bb];
    }
    __syncthreads();

    if (t < ND) {
        float ar[4] = {0.f, 0.f, 0.f, 0.f};
        float ac[4] = {0.f, 0.f, 0.f, 0.f};
        for (int b = 0; b < NB; b++) {
            float f = g_fu[b * ND + t];
            float4 p = *(const float4*)&Pr[b][0];
            float4 q = *(const float4*)&Qr[b][0];
            ar[0] += p.x * f; ar[1] += p.y * f; ar[2] += p.z * f; ar[3] += p.w * f;
            ac[0] += q.x * f; ac[1] += q.y * f; ac[2] += q.z * f; ac[3] += q.w * f;
        }
#pragma unroll
        for (int ci = 0; ci < 4; ci++) {
            sA[0][t][ci] = sigmoidf_(ar[ci]);
            sA[1][t][ci] = sigmoidf_(ac[ci]);
        }
    }
    __syncthreads();

    if (t < 2 * NH) {
        int which = t / NH, h = t % NH;
        const float* WmT = which ? g_WmcT : g_WmrT;
        float bb = which ? bmc[h] : bmr[h];
        float a[4] = {bb, bb, bb, bb};
        for (int d = 0; d < ND; d++) {
            float w = WmT[d * NH + h];
            float4 s = *(const float4*)&sA[which][d][0];
            a[0] += w * s.x; a[1] += w * s.y; a[2] += w * s.z; a[3] += w * s.w;
        }
        float wj = Wj[h];
#pragma unroll
        for (int ci = 0; ci < 4; ci++) red[t][ci] = wj * sigmoidf_(a[ci]);
    }
    __syncthreads();

    if (t < 4) {
        float s = 0.f;
        for (int e = 0; e < 2 * NH; e++) s += red[e][t];
        g_y23[c0 + t] = s + 2.f * bj[0];
    }
}

// ---------------- launch -----------------------------------------------------
extern "C" void kernel_launch(void* const* d_in, const int* in_sizes, int n_in,
                              void* d_out, int out_size) {
    const float* utt      = (const float*)d_in[0];
    const float* sys_s    = (const float*)d_in[1];
    const float* conf_s   = (const float*)d_in[2];
    const float* conf_v   = (const float*)d_in[3];
    const float* ypast    = (const float*)d_in[4];
    const float* slot_emb = (const float*)d_in[5];
    const float* val_emb  = (const float*)d_in[6];
    const float* Wc       = (const float*)d_in[7];
    const float* bc       = (const float*)d_in[8];
    const float* cw1      = (const float*)d_in[9];
    const float* cb1      = (const float*)d_in[10];
    const float* cw2      = (const float*)d_in[11];
    const float* cb2      = (const float*)d_in[12];
    const float* cw3      = (const float*)d_in[13];
    const float* cb3      = (const float*)d_in[14];
    const float* Wd       = (const float*)d_in[15];
    const float* bd       = (const float*)d_in[16];
    const float* Wmr      = (const float*)d_in[17];
    const float* bmr      = (const float*)d_in[18];
    const float* Wmc      = (const float*)d_in[19];
    const float* bmc      = (const float*)d_in[20];
    const float* Wj       = (const float*)d_in[21];
    const float* bj       = (const float*)d_in[22];
    float* out = (float*)d_out;
    (void)in_sizes; (void)n_in; (void)out_size;

    // REAL device addresses (host-shadow/ATS trap).
    float *p_G, *p_cand;
    __nv_bfloat16 *p_utt_h, *p_utt_l, *p_Wcat_h, *p_Wcat_l;
    __nv_bfloat16 *p_catSV_h, *p_catSV_l, *p_Wc_h, *p_Wc_l;
    cudaGetSymbolAddress((void**)&p_G,       g_G);
    cudaGetSymbolAddress((void**)&p_cand,    g_cand);
    cudaGetSymbolAddress((void**)&p_utt_h,   g_utt_h);
    cudaGetSymbolAddress((void**)&p_utt_l,   g_utt_l);
    cudaGetSymbolAddress((void**)&p_Wcat_h,  g_Wcat_h);
    cudaGetSymbolAddress((void**)&p_Wcat_l,  g_Wcat_l);
    cudaGetSymbolAddress((void**)&p_catSV_h, g_catSV_h);
    cudaGetSymbolAddress((void**)&p_catSV_l, g_catSV_l);
    cudaGetSymbolAddress((void**)&p_Wc_h,    g_Wc_h);
    cudaGetSymbolAddress((void**)&p_Wc_l,    g_Wc_l);

    const int GEMM_SMEM  = 2 * BUFU * 4 + 8 * 16 * WSLD * 4;  // 81920+10240=92160
    const int FINAL_SMEM = 128 * CLD * 4;                     // 67584
    cudaFuncSetAttribute(wgemm_kernel,
                         cudaFuncAttributeMaxDynamicSharedMemorySize, GEMM_SMEM);
    cudaFuncSetAttribute(ptt_kernel,
                         cudaFuncAttributeMaxDynamicSharedMemorySize, GEMM_SMEM);
    cudaFuncSetAttribute(final_wmma_kernel,
                         cudaFuncAttributeMaxDynamicSharedMemorySize, FINAL_SMEM);

    // 1. pack Wcat fp32 + WmT
    pack_kernel<<<(540000 + 255) / 256, 256>>>(cw1, cw2, cw3, Wmr, Wmc);
    // 2. presplit utt
    presplitA_kernel<<<(5120 * 300 + 255) / 256, 256>>>(utt);
    // 3. presplit all statics (needs pack)
    presplitB_kernel<<<(PREB_TOTAL + 255) / 256, 256>>>(
        slot_emb, val_emb, Wc, sys_s, conf_s, conf_v, Wd);
    // 4. PTT (one launch)
    ptt_kernel<<<dim3(3, 8), 256, GEMM_SMEM>>>();
    // 5. cand = sigmoid(catSV @ Wc^T + bc)
    wgemm_kernel<<<dim3(3, 8), 256, GEMM_SMEM>>>(
        p_catSV_h, p_catSV_l, KP600, p_Wc_h, p_Wc_l, KP600,
        p_cand, 300, 19, bc, 1, NC, ND, 1);
    // 6. conv GEMM  <-- ncu -s 5 -c 1 captures THIS launch
    wgemm_kernel<<<dim3(15, 40), 256, GEMM_SMEM>>>(
        p_utt_h, p_utt_l, KP300, p_Wcat_h, p_Wcat_l, KP300,
        p_G, GLD, 10, nullptr, 0, 5120, 1800, 0);
    // 7. pool -> fu
    pool_kernel<<<NB, 320>>>(cb1, cb2, cb3);
    // 8. gates (needs PTT + fu)
    gates_kernel<<<NC / 4, 384>>>(bmr, bmc, Wj, bj);
    // 9. fused y1 + combine + output
    final_wmma_kernel<<<dim3(8, NB), 256, FINAL_SMEM>>>(Wj, bd, bj, ypast, out);
}